// round 11
// baseline (speedup 1.0000x reference)
#include <cuda_runtime.h>
#include <cuda_bf16.h>
#include <mma.h>
#include <math_constants.h>

using namespace nvcuda;

#define E_ 1024
#define W_ 1024
#define B_ 4
#define H_ 16
#define D_ 64
#define BH_ 64

typedef unsigned long long u64t;
typedef unsigned int u32t;

// ---------------- scratch (allocation-free; symbols only referenced in device code) ----------------
__device__ __nv_bfloat16 g_qkv_hi[12ull * E_ * W_];   // [z=p*4+b][e][w]; p:0=K,1=Q,2=V
__device__ __nv_bfloat16 g_qkv_lo[12ull * E_ * W_];
__device__ __nv_bfloat16 g_o_hi[4ull * E_ * W_];
__device__ __nv_bfloat16 g_o_lo[4ull * E_ * W_];

// ---------------- fp32 -> bf16 hi/lo split ----------------
__device__ __forceinline__ void split4(float4 v, uint2& uh, uint2& ul)
{
    __nv_bfloat16 h0 = __float2bfloat16_rn(v.x);
    __nv_bfloat16 h1 = __float2bfloat16_rn(v.y);
    __nv_bfloat16 h2 = __float2bfloat16_rn(v.z);
    __nv_bfloat16 h3 = __float2bfloat16_rn(v.w);
    __nv_bfloat16 l0 = __float2bfloat16_rn(v.x - __bfloat162float(h0));
    __nv_bfloat16 l1 = __float2bfloat16_rn(v.y - __bfloat162float(h1));
    __nv_bfloat16 l2 = __float2bfloat16_rn(v.z - __bfloat162float(h2));
    __nv_bfloat16 l3 = __float2bfloat16_rn(v.w - __bfloat162float(h3));
    uh.x = (u32t)__bfloat16_as_ushort(h0) | ((u32t)__bfloat16_as_ushort(h1) << 16);
    uh.y = (u32t)__bfloat16_as_ushort(h2) | ((u32t)__bfloat16_as_ushort(h3) << 16);
    ul.x = (u32t)__bfloat16_as_ushort(l0) | ((u32t)__bfloat16_as_ushort(l1) << 16);
    ul.y = (u32t)__bfloat16_as_ushort(l2) | ((u32t)__bfloat16_as_ushort(l3) << 16);
}

// store 8 fp32 (two float4) as split bf16 to dh/dl at element index idx
__device__ __forceinline__ void store_split8(
    __nv_bfloat16* dh, __nv_bfloat16* dl, int idx, float4 v0, float4 v1)
{
    uint2 h0, l0, h1, l1;
    split4(v0, h0, l0);
    split4(v1, h1, l1);
    *(uint2*)(dh + idx)     = h0;
    *(uint2*)(dh + idx + 4) = h1;
    *(uint2*)(dl + idx)     = l0;
    *(uint2*)(dl + idx + 4) = l1;
}

// ---------------- wmma typedefs ----------------
typedef wmma::fragment<wmma::matrix_a, 16, 16, 16, __nv_bfloat16, wmma::row_major> FragA;
typedef wmma::fragment<wmma::matrix_a, 16, 16, 16, __nv_bfloat16, wmma::col_major> FragAT;
typedef wmma::fragment<wmma::matrix_b, 16, 16, 16, __nv_bfloat16, wmma::row_major> FragB;
typedef wmma::fragment<wmma::accumulator, 16, 16, 16, float> FragC;

// ---------------- wmma bf16 3-term GEMM with in-kernel fp32->hi/lo conversion ----------------
// A: fp32 [M][K] (converted in load phase). B: fp32 [K][N] if B_FP32, else bf16 hi/lo pair.
// C: fp32 + bias if Cf, else split to Ch/Cl.
#define AK 40
#define BN 136
#define A_BUF 5120
#define B_BUF 4352
#define OFF_AL_B 20480
#define OFF_BH_B 40960
#define OFF_BL_B 58368
#define SMEM_MMA 75776

template<bool B_FP32>
__device__ __forceinline__ void mma_gemm_body(
    const float* __restrict__ Af,
    const float* __restrict__ Bf,
    const __nv_bfloat16* __restrict__ Bh, const __nv_bfloat16* __restrict__ Bl,
    float* __restrict__ Cf, __nv_bfloat16* __restrict__ Ch, __nv_bfloat16* __restrict__ Cl,
    const float* __restrict__ bias)
{
    extern __shared__ __align__(128) char smem[];
    __nv_bfloat16* sAh = (__nv_bfloat16*)(smem);
    __nv_bfloat16* sAl = (__nv_bfloat16*)(smem + OFF_AL_B);
    __nv_bfloat16* sBh = (__nv_bfloat16*)(smem + OFF_BH_B);
    __nv_bfloat16* sBl = (__nv_bfloat16*)(smem + OFF_BL_B);
    float* stage = (float*)smem;

    const int tid = threadIdx.x;
    const int w = tid >> 5;
    const int wm = w & 3;
    const int wn = w >> 2;
    const int m0 = blockIdx.y * 128;
    const int n0 = blockIdx.x * 128;

    const int ar = tid >> 1, ak = (tid & 1) * 16;   // A: 128 rows x 32 k (16 fp32/thread)
    const int bk = tid >> 3, bn = (tid & 7) * 16;   // B: 32 k x 128 n (16 elems/thread)

    const float* gA = Af + (size_t)(m0 + ar) * 1024 + ak;
    const float* gBf = B_FP32 ? (Bf + (size_t)bk * 1024 + n0 + bn) : nullptr;
    const __nv_bfloat16* gBh = B_FP32 ? nullptr : (Bh + (size_t)bk * 1024 + n0 + bn);
    const __nv_bfloat16* gBl = B_FP32 ? nullptr : (Bl + (size_t)bk * 1024 + n0 + bn);

    FragC acc[2][4];
#pragma unroll
    for (int mi = 0; mi < 2; mi++)
#pragma unroll
        for (int ni = 0; ni < 4; ni++) wmma::fill_fragment(acc[mi][ni], 0.0f);

    // preload stage 0
    {
        float4 a0 = *(const float4*)(gA);
        float4 a1 = *(const float4*)(gA + 4);
        float4 a2 = *(const float4*)(gA + 8);
        float4 a3 = *(const float4*)(gA + 12);
        store_split8(sAh, sAl, ar * AK + ak, a0, a1);
        store_split8(sAh, sAl, ar * AK + ak + 8, a2, a3);
        if (B_FP32) {
            float4 b0 = *(const float4*)(gBf);
            float4 b1 = *(const float4*)(gBf + 4);
            float4 b2 = *(const float4*)(gBf + 8);
            float4 b3 = *(const float4*)(gBf + 12);
            store_split8(sBh, sBl, bk * BN + bn, b0, b1);
            store_split8(sBh, sBl, bk * BN + bn + 8, b2, b3);
        } else {
            *(uint4*)(&sBh[bk * BN + bn])     = *(const uint4*)(gBh);
            *(uint4*)(&sBh[bk * BN + bn + 8]) = *(const uint4*)(gBh + 8);
            *(uint4*)(&sBl[bk * BN + bn])     = *(const uint4*)(gBl);
            *(uint4*)(&sBl[bk * BN + bn + 8]) = *(const uint4*)(gBl + 8);
        }
    }
    __syncthreads();

    int buf = 0;
    for (int kt = 32; kt <= 1024; kt += 32) {
        const bool has = (kt < 1024);
        float4 a0, a1, a2, a3, b0, b1, b2, b3;
        uint4 ubh0, ubh1, ubl0, ubl1;
        if (has) {
            a0 = *(const float4*)(gA + kt);
            a1 = *(const float4*)(gA + kt + 4);
            a2 = *(const float4*)(gA + kt + 8);
            a3 = *(const float4*)(gA + kt + 12);
            if (B_FP32) {
                b0 = *(const float4*)(gBf + (size_t)kt * 1024);
                b1 = *(const float4*)(gBf + (size_t)kt * 1024 + 4);
                b2 = *(const float4*)(gBf + (size_t)kt * 1024 + 8);
                b3 = *(const float4*)(gBf + (size_t)kt * 1024 + 12);
            } else {
                ubh0 = *(const uint4*)(gBh + (size_t)kt * 1024);
                ubh1 = *(const uint4*)(gBh + (size_t)kt * 1024 + 8);
                ubl0 = *(const uint4*)(gBl + (size_t)kt * 1024);
                ubl1 = *(const uint4*)(gBl + (size_t)kt * 1024 + 8);
            }
        }

        const int ab = buf * A_BUF, bb = buf * B_BUF;
#pragma unroll
        for (int kk = 0; kk < 32; kk += 16) {
            FragA fah[2], fal[2];
#pragma unroll
            for (int mi = 0; mi < 2; mi++) {
                wmma::load_matrix_sync(fah[mi], &sAh[ab + (wm * 32 + mi * 16) * AK + kk], AK);
                wmma::load_matrix_sync(fal[mi], &sAl[ab + (wm * 32 + mi * 16) * AK + kk], AK);
            }
#pragma unroll
            for (int ni = 0; ni < 4; ni++) {
                FragB fbh, fbl;
                wmma::load_matrix_sync(fbh, &sBh[bb + kk * BN + wn * 64 + ni * 16], BN);
                wmma::load_matrix_sync(fbl, &sBl[bb + kk * BN + wn * 64 + ni * 16], BN);
#pragma unroll
                for (int mi = 0; mi < 2; mi++) {
                    wmma::mma_sync(acc[mi][ni], fah[mi], fbh, acc[mi][ni]);
                    wmma::mma_sync(acc[mi][ni], fah[mi], fbl, acc[mi][ni]);
                    wmma::mma_sync(acc[mi][ni], fal[mi], fbh, acc[mi][ni]);
                }
            }
        }

        if (has) {
            const int nb = buf ^ 1;
            const int nab = nb * A_BUF, nbb = nb * B_BUF;
            store_split8(sAh + nab, sAl + nab, ar * AK + ak, a0, a1);
            store_split8(sAh + nab, sAl + nab, ar * AK + ak + 8, a2, a3);
            if (B_FP32) {
                store_split8(sBh + nbb, sBl + nbb, bk * BN + bn, b0, b1);
                store_split8(sBh + nbb, sBl + nbb, bk * BN + bn + 8, b2, b3);
            } else {
                *(uint4*)(&sBh[nbb + bk * BN + bn])     = ubh0;
                *(uint4*)(&sBh[nbb + bk * BN + bn + 8]) = ubh1;
                *(uint4*)(&sBl[nbb + bk * BN + bn])     = ubl0;
                *(uint4*)(&sBl[nbb + bk * BN + bn + 8]) = ubl1;
            }
        }
        __syncthreads();
        buf ^= 1;
    }

#pragma unroll
    for (int mi = 0; mi < 2; mi++)
#pragma unroll
        for (int ni = 0; ni < 4; ni++)
            wmma::store_matrix_sync(&stage[(wm * 32 + mi * 16) * 132 + wn * 64 + ni * 16],
                                    acc[mi][ni], 132, wmma::mem_row_major);
    __syncthreads();

    {
        const int r = tid >> 1;
        const int hf = (tid & 1) * 64;
        const float* src = stage + r * 132 + hf;
        if (Cf) {
            const float bv = bias ? bias[m0 + r] : 0.f;
            float* dst = Cf + (size_t)(m0 + r) * 1024 + n0 + hf;
#pragma unroll
            for (int j = 0; j < 16; j++) {
                float4 v = *(const float4*)(src + j * 4);
                v.x += bv; v.y += bv; v.z += bv; v.w += bv;
                *(float4*)(dst + j * 4) = v;
            }
        } else {
            size_t o = (size_t)(m0 + r) * 1024 + n0 + hf;
#pragma unroll
            for (int j = 0; j < 16; j++) {
                uint2 uh, ul;
                split4(*(const float4*)(src + j * 4), uh, ul);
                *(uint2*)(Ch + o + j * 4) = uh;
                *(uint2*)(Cl + o + j * 4) = ul;
            }
        }
    }
}

// proj: A = L_p (fp32 arg), B = x[z] (fp32 arg), C -> g_qkv hi/lo
__global__ __launch_bounds__(256) void k_proj_mma(
    const float* __restrict__ LQ, const float* __restrict__ LK,
    const float* __restrict__ LV, const float* __restrict__ x)
{
    int z = blockIdx.z;
    int p = z >> 2;   // 0=K,1=Q,2=V
    const float* A = (p == 0) ? LK : (p == 1) ? LQ : LV;
    mma_gemm_body<true>(A, x + (size_t)z * E_ * W_, nullptr, nullptr,
                        nullptr, g_qkv_hi + (size_t)z * E_ * W_, g_qkv_lo + (size_t)z * E_ * W_,
                        nullptr);
}

// final: A = M (fp32 arg), B = g_o hi/lo, C -> out + bias
__global__ __launch_bounds__(256) void k_final_mma(
    const float* __restrict__ Mw, const float* __restrict__ bias, float* __restrict__ out)
{
    int b = blockIdx.z;
    mma_gemm_body<false>(Mw, nullptr,
                         g_o_hi + (size_t)b * E_ * W_, g_o_lo + (size_t)b * E_ * W_,
                         out + (size_t)b * E_ * W_, nullptr, nullptr, bias);
}

// ---------------- fused attention (single pass, no max shift) ----------------
#define FZ_LD 136
#define OFS_KH 0
#define OFS_KL 17408
#define OFS_QH 34816
#define OFS_QL 52224
#define OFS_PH 34816
#define OFS_PL 69632
#define OFS_S  104448
#define OFS_VH 172032
#define OFS_VL 189440
#define OFS_M  206848
#define OFS_L  207360
#define OFS_PART 207872
#define SMEM_FZ 209920

__global__ __launch_bounds__(256) void k_attn_fused()
{
    extern __shared__ __align__(128) char smem[];
    __nv_bfloat16* sKh = (__nv_bfloat16*)(smem + OFS_KH);
    __nv_bfloat16* sKl = (__nv_bfloat16*)(smem + OFS_KL);
    __nv_bfloat16* sQh = (__nv_bfloat16*)(smem + OFS_QH);
    __nv_bfloat16* sQl = (__nv_bfloat16*)(smem + OFS_QL);
    __nv_bfloat16* sPh = (__nv_bfloat16*)(smem + OFS_PH);   // overlays Q region
    __nv_bfloat16* sPl = (__nv_bfloat16*)(smem + OFS_PL);
    float* sS = (float*)(smem + OFS_S);                      // [128][132]
    __nv_bfloat16* sVh = (__nv_bfloat16*)(smem + OFS_VH);
    __nv_bfloat16* sVl = (__nv_bfloat16*)(smem + OFS_VL);
    float* sM = (float*)(smem + OFS_M);                      // inv scale staging
    float* sL = (float*)(smem + OFS_L);
    float* sPart = (float*)(smem + OFS_PART);                // [4][128]

    const int kt = 7 - blockIdx.x;          // big tiles first
    const int n0 = kt * 128;
    const int z = blockIdx.y;
    const int b = z >> 4, h = z & 15;
    const size_t qoff = (size_t)((4 + b) * E_ + h * D_) * W_;
    const size_t koff = (size_t)(b * E_ + h * D_) * W_;
    const size_t voff = (size_t)((8 + b) * E_ + h * D_) * W_;

    const int tid = threadIdx.x;
    const int w = tid >> 5;

    const int lrow = tid >> 2;              // 0..63 (d)
    const int lcb  = (tid & 3) * 32;

    // K tile (persistent)
#pragma unroll
    for (int u = 0; u < 4; u++) {
        int col = lcb + u * 8;
        *(uint4*)(&sKh[lrow * FZ_LD + col]) = *(const uint4*)(g_qkv_hi + koff + (size_t)lrow * W_ + n0 + col);
        *(uint4*)(&sKl[lrow * FZ_LD + col]) = *(const uint4*)(g_qkv_lo + koff + (size_t)lrow * W_ + n0 + col);
    }
    if (tid < 128) sL[tid] = 0.f;

    const int cp = (tid & 63) * 2;          // owns cols cp, cp+1
    const int rq = tid >> 6;                // row block (x32)

    const int swm = w & 3, swn = w >> 2;    // scores warp tile
    const int awm = w & 1, awn = w >> 1;    // AV warp tile

    FragC oacc[2][2];
#pragma unroll
    for (int mi = 0; mi < 2; mi++)
#pragma unroll
        for (int ni = 0; ni < 2; ni++) wmma::fill_fragment(oacc[mi][ni], 0.0f);

    for (int t = 0; t <= kt; t++) {
        __syncthreads();   // previous AV reads of P/V done
        // V gmem loads -> regs (stored to smem during exp phase; hides latency)
        uint4 vh[4], vl[4];
#pragma unroll
        for (int u = 0; u < 4; u++) {
            int col = lcb + u * 8;
            vh[u] = *(const uint4*)(g_qkv_hi + voff + (size_t)lrow * W_ + t * 128 + col);
            vl[u] = *(const uint4*)(g_qkv_lo + voff + (size_t)lrow * W_ + t * 128 + col);
        }
        // Q tile -> smem
#pragma unroll
        for (int u = 0; u < 4; u++) {
            int col = lcb + u * 8;
            *(uint4*)(&sQh[lrow * FZ_LD + col]) = *(const uint4*)(g_qkv_hi + qoff + (size_t)lrow * W_ + t * 128 + col);
            *(uint4*)(&sQl[lrow * FZ_LD + col]) = *(const uint4*)(g_qkv_lo + qoff + (size_t)lrow * W_ + t * 128 + col);
        }
        __syncthreads();

        // S = Q^T K (3-term)
        FragC sacc[2][4];
#pragma unroll
        for (int mi = 0; mi < 2; mi++)
#pragma unroll
            for (int ni = 0; ni < 4; ni++) wmma::fill_fragment(sacc[mi][ni], 0.0f);
#pragma unroll
        for (int ks = 0; ks < 64; ks += 16) {
            FragAT fah[2], fal[2];
#pragma unroll
            for (int mi = 0; mi < 2; mi++) {
                wmma::load_matrix_sync(fah[mi], &sQh[ks * FZ_LD + swm * 32 + mi * 16], FZ_LD);
                wmma::load_matrix_sync(fal[mi], &sQl[ks * FZ_LD + swm * 32 + mi * 16], FZ_LD);
            }
#pragma unroll
            for (int ni = 0; ni < 4; ni++) {
                FragB fbh, fbl;
                wmma::load_matrix_sync(fbh, &sKh[ks * FZ_LD + swn * 64 + ni * 16], FZ_LD);
                wmma::load_matrix_sync(fbl, &sKl[ks * FZ_LD + swn * 64 + ni * 16], FZ_LD);
#pragma unroll
                for (int mi = 0; mi < 2; mi++) {
                    wmma::mma_sync(sacc[mi][ni], fah[mi], fbh, sacc[mi][ni]);
                    wmma::mma_sync(sacc[mi][ni], fah[mi], fbl, sacc[mi][ni]);
                    wmma::mma_sync(sacc[mi][ni], fal[mi], fbh, sacc[mi][ni]);
                }
            }
        }
#pragma unroll
        for (int mi = 0; mi < 2; mi++)
#pragma unroll
            for (int ni = 0; ni < 4; ni++)
                wmma::store_matrix_sync(&sS[(swm * 32 + mi * 16) * 132 + swn * 64 + ni * 16],
                                        sacc[mi][ni], 132, wmma::mem_row_major);
        __syncthreads();   // sS ready; Q reads done (P overlays Q region)

        // P = exp(S), l partials; V regs -> smem (V region idle here)
        float l0 = 0.f, l1 = 0.f;
        const bool diag = (t == kt);
        for (int r = 0; r < 32; r++) {
            int ql = rq * 32 + r;
            float2 v = *(const float2*)(&sS[ql * 132 + cp]);
            float p0 = (!diag || ql <= cp)     ? __expf(v.x) : 0.f;
            float p1 = (!diag || ql <= cp + 1) ? __expf(v.y) : 0.f;
            l0 += p0; l1 += p1;
            __nv_bfloat16 h0 = __float2bfloat16_rn(p0);
            __nv_bfloat16 h1 = __float2bfloat16_rn(p1);
            __nv_bfloat16 g0 = __float2bfloat16_rn(p0 - __bfloat162float(h0));
            __nv_bfloat16 g1 = __float2bfloat16_rn(p1 - __bfloat162float(h1));
            *(u32t*)(&sPh[ql * FZ_LD + cp]) = (u32t)__bfloat16_as_ushort(h0) | ((u32t)__bfloat16_as_ushort(h1) << 16);
            *(u32t*)(&sPl[ql * FZ_LD + cp]) = (u32t)__bfloat16_as_ushort(g0) | ((u32t)__bfloat16_as_ushort(g1) << 16);
        }
#pragma unroll
        for (int u = 0; u < 4; u++) {
            int col = lcb + u * 8;
            *(uint4*)(&sVh[lrow * FZ_LD + col]) = vh[u];
            *(uint4*)(&sVl[lrow * FZ_LD + col]) = vl[u];
        }
        sPart[rq * 128 + cp]     = l0;
        sPart[rq * 128 + cp + 1] = l1;
        __syncthreads();   // P + V + l partials ready
        if (tid < 128)
            sL[tid] += sPart[tid] + sPart[128 + tid] + sPart[256 + tid] + sPart[384 + tid];

        // O += V @ P (3-term)
#pragma unroll
        for (int ks = 0; ks < 128; ks += 16) {
            FragA fvh[2], fvl[2];
#pragma unroll
            for (int mi = 0; mi < 2; mi++) {
                wmma::load_matrix_sync(fvh[mi], &sVh[(awm * 32 + mi * 16) * FZ_LD + ks], FZ_LD);
                wmma::load_matrix_sync(fvl[mi], &sVl[(awm * 32 + mi * 16) * FZ_LD + ks], FZ_LD);
            }
#pragma unroll
            for (int ni = 0; ni < 2; ni++) {
                FragB fph, fpl;
                wmma::load_matrix_sync(fph, &sPh[ks * FZ_LD + awn * 32 + ni * 16], FZ_LD);
                wmma::load_matrix_sync(fpl, &sPl[ks * FZ_LD + awn * 32 + ni * 16], FZ_LD);
#pragma unroll
                for (int mi = 0; mi < 2; mi++) {
                    wmma::mma_sync(oacc[mi][ni], fvh[mi], fph, oacc[mi][ni]);
                    wmma::mma_sync(oacc[mi][ni], fvh[mi], fpl, oacc[mi][ni]);
                    wmma::mma_sync(oacc[mi][ni], fvl[mi], fph, oacc[mi][ni]);
                }
            }
        }
    }
    __syncthreads();

    // epilogue: O frags -> sS staging, scale by 1/(32*l), split to o_hi/lo
#pragma unroll
    for (int mi = 0; mi < 2; mi++)
#pragma unroll
        for (int ni = 0; ni < 2; ni++)
            wmma::store_matrix_sync(&sS[(awm * 32 + mi * 16) * 132 + awn * 32 + ni * 16],
                                    oacc[mi][ni], 132, wmma::mem_row_major);
    if (tid < 128) sM[tid] = 1.0f / (32.0f * sL[tid]);
    __syncthreads();

    {
        const size_t obase = (size_t)(b * E_ + h * D_ + lrow) * W_ + n0;
#pragma unroll
        for (int u = 0; u < 8; u++) {
            int col = lcb + u * 4;
            float4 v = *(const float4*)(&sS[lrow * 132 + col]);
            v.x *= sM[col]; v.y *= sM[col + 1]; v.z *= sM[col + 2]; v.w *= sM[col + 3];
            uint2 uh, ul;
            split4(v, uh, ul);
            *(uint2*)(g_o_hi + obase + col) = uh;
            *(uint2*)(g_o_lo + obase + col) = ul;
        }
    }
}

// ---------------------------------------------------------------------------
extern "C" void kernel_launch(void* const* d_in, const int* in_sizes, int n_in,
                              void* d_out, int out_size)
{
    const float* x  = (const float*)d_in[0];
    const float* LQ = (const float*)d_in[1];
    const float* LK = (const float*)d_in[2];
    const float* LV = (const float*)d_in[3];
    const float* Mw = (const float*)d_in[4];
    const float* bv = (const float*)d_in[5];
    float* out = (float*)d_out;

    cudaFuncSetAttribute(k_proj_mma,   cudaFuncAttributeMaxDynamicSharedMemorySize, SMEM_MMA);
    cudaFuncSetAttribute(k_final_mma,  cudaFuncAttributeMaxDynamicSharedMemorySize, SMEM_MMA);
    cudaFuncSetAttribute(k_attn_fused, cudaFuncAttributeMaxDynamicSharedMemorySize, SMEM_FZ);

    dim3 blk(256);

    k_proj_mma  <<<dim3(8, 8, 12), blk, SMEM_MMA>>>(LQ, LK, LV, x);
    k_attn_fused<<<dim3(8, 64),    blk, SMEM_FZ>>>();
    k_final_mma <<<dim3(8, 8, 4),  blk, SMEM_MMA>>>(Mw, bv, out);
}

// round 12
// speedup vs baseline: 1.1815x; 1.1815x over previous
#include <cuda_runtime.h>
#include <cuda_bf16.h>
#include <mma.h>
#include <math_constants.h>

using namespace nvcuda;

#define E_ 1024
#define W_ 1024
#define B_ 4
#define H_ 16
#define D_ 64
#define BH_ 64

typedef unsigned long long u64t;
typedef unsigned int u32t;

// ---------------- scratch (symbols only referenced in device code) ----------------
__device__ __nv_bfloat16 g_qkv_hi[12ull * E_ * W_];   // [z=p*4+b][e][w]; p:0=K,1=Q,2=V
__device__ __nv_bfloat16 g_qkv_lo[12ull * E_ * W_];
__device__ __nv_bfloat16 g_w_hi[4ull * E_ * E_];      // [p: K,Q,V,M][e][f]
__device__ __nv_bfloat16 g_w_lo[4ull * E_ * E_];
__device__ __nv_bfloat16 g_x_hi[12ull * E_ * W_];
__device__ __nv_bfloat16 g_x_lo[12ull * E_ * W_];
__device__ __nv_bfloat16 g_o_hi[4ull * E_ * W_];
__device__ __nv_bfloat16 g_o_lo[4ull * E_ * W_];

// ---------------- helpers ----------------
__device__ __forceinline__ u32t smem_u32(const void* p) {
    u32t a;
    asm("{ .reg .u64 t; cvta.to.shared.u64 t, %1; cvt.u32.u64 %0, t; }" : "=r"(a) : "l"(p));
    return a;
}
__device__ __forceinline__ void cp16(u32t dst, const void* src) {
    asm volatile("cp.async.cg.shared.global [%0], [%1], 16;" :: "r"(dst), "l"(src));
}
__device__ __forceinline__ void cp_commit() { asm volatile("cp.async.commit_group;" ::: "memory"); }
__device__ __forceinline__ void cp_wait1()  { asm volatile("cp.async.wait_group 1;" ::: "memory"); }
__device__ __forceinline__ void cp_wait0()  { asm volatile("cp.async.wait_group 0;" ::: "memory"); }

__device__ __forceinline__ void split4(float4 v, uint2& uh, uint2& ul)
{
    __nv_bfloat16 h0 = __float2bfloat16_rn(v.x);
    __nv_bfloat16 h1 = __float2bfloat16_rn(v.y);
    __nv_bfloat16 h2 = __float2bfloat16_rn(v.z);
    __nv_bfloat16 h3 = __float2bfloat16_rn(v.w);
    __nv_bfloat16 l0 = __float2bfloat16_rn(v.x - __bfloat162float(h0));
    __nv_bfloat16 l1 = __float2bfloat16_rn(v.y - __bfloat162float(h1));
    __nv_bfloat16 l2 = __float2bfloat16_rn(v.z - __bfloat162float(h2));
    __nv_bfloat16 l3 = __float2bfloat16_rn(v.w - __bfloat162float(h3));
    uh.x = (u32t)__bfloat16_as_ushort(h0) | ((u32t)__bfloat16_as_ushort(h1) << 16);
    uh.y = (u32t)__bfloat16_as_ushort(h2) | ((u32t)__bfloat16_as_ushort(h3) << 16);
    ul.x = (u32t)__bfloat16_as_ushort(l0) | ((u32t)__bfloat16_as_ushort(l1) << 16);
    ul.y = (u32t)__bfloat16_as_ushort(l2) | ((u32t)__bfloat16_as_ushort(l3) << 16);
}

__global__ __launch_bounds__(256) void k_split_w(const float* __restrict__ s, int p)
{
    size_t i = ((size_t)blockIdx.x * 256 + threadIdx.x) * 4;
    uint2 uh, ul;
    split4(*(const float4*)(s + i), uh, ul);
    size_t o = (size_t)p * E_ * E_ + i;
    *(uint2*)(g_w_hi + o) = uh;
    *(uint2*)(g_w_lo + o) = ul;
}

__global__ __launch_bounds__(256) void k_split_x(const float* __restrict__ s)
{
    size_t i = ((size_t)blockIdx.x * 256 + threadIdx.x) * 4;
    uint2 uh, ul;
    split4(*(const float4*)(s + i), uh, ul);
    *(uint2*)(g_x_hi + i) = uh;
    *(uint2*)(g_x_lo + i) = ul;
}

// ---------------- wmma typedefs ----------------
typedef wmma::fragment<wmma::matrix_a, 16, 16, 16, __nv_bfloat16, wmma::row_major> FragA;
typedef wmma::fragment<wmma::matrix_a, 16, 16, 16, __nv_bfloat16, wmma::col_major> FragAT;
typedef wmma::fragment<wmma::matrix_b, 16, 16, 16, __nv_bfloat16, wmma::row_major> FragB;
typedef wmma::fragment<wmma::accumulator, 16, 16, 16, float> FragC;

// ---------------- wmma bf16 3-term GEMM, cp.async double buffer, 2 CTAs/SM ----------------
#define AK 40
#define BN 136
#define A_BUF 5120
#define B_BUF 4352
#define OFF_AL_B 20480
#define OFF_BH_B 40960
#define OFF_BL_B 58368
#define STAGE_B 75776          // not used for stride; buffers indexed per-array
#define SMEM_MMA 75776

__device__ __forceinline__ void mma_gemm_body(
    const __nv_bfloat16* __restrict__ Ah, const __nv_bfloat16* __restrict__ Al,
    const __nv_bfloat16* __restrict__ Bh, const __nv_bfloat16* __restrict__ Bl,
    float* __restrict__ Cf, __nv_bfloat16* __restrict__ Ch, __nv_bfloat16* __restrict__ Cl,
    const float* __restrict__ bias)
{
    extern __shared__ __align__(128) char smem[];
    __nv_bfloat16* sAh = (__nv_bfloat16*)(smem);
    __nv_bfloat16* sAl = (__nv_bfloat16*)(smem + OFF_AL_B);
    __nv_bfloat16* sBh = (__nv_bfloat16*)(smem + OFF_BH_B);
    __nv_bfloat16* sBl = (__nv_bfloat16*)(smem + OFF_BL_B);
    float* stage = (float*)smem;

    const u32t uAh = smem_u32(sAh);
    const u32t uAl = smem_u32(sAl);
    const u32t uBh = smem_u32(sBh);
    const u32t uBl = smem_u32(sBl);

    const int tid = threadIdx.x;
    const int w = tid >> 5;
    const int wm = w & 3;
    const int wn = w >> 2;
    const int m0 = blockIdx.y * 128;
    const int n0 = blockIdx.x * 128;

    const int ar = tid >> 1, ak = (tid & 1) * 16;   // A: 128 rows x 32 k
    const int bk = tid >> 3, bn = (tid & 7) * 16;   // B: 32 k x 128 n

    const __nv_bfloat16* gAh = Ah + (size_t)(m0 + ar) * 1024 + ak;
    const __nv_bfloat16* gAl = Al + (size_t)(m0 + ar) * 1024 + ak;
    const __nv_bfloat16* gBh = Bh + (size_t)bk * 1024 + n0 + bn;
    const __nv_bfloat16* gBl = Bl + (size_t)bk * 1024 + n0 + bn;

    const u32t aDst = (u32t)((ar * AK + ak) * 2);
    const u32t bDst = (u32t)((bk * BN + bn) * 2);

    FragC acc[2][4];
#pragma unroll
    for (int mi = 0; mi < 2; mi++)
#pragma unroll
        for (int ni = 0; ni < 4; ni++) wmma::fill_fragment(acc[mi][ni], 0.0f);

    // prologue: stage 0 via cp.async
    {
        cp16(uAh + aDst,      gAh);
        cp16(uAh + aDst + 16, gAh + 8);
        cp16(uAl + aDst,      gAl);
        cp16(uAl + aDst + 16, gAl + 8);
        cp16(uBh + bDst,      gBh);
        cp16(uBh + bDst + 16, gBh + 8);
        cp16(uBl + bDst,      gBl);
        cp16(uBl + bDst + 16, gBl + 8);
        cp_commit();
    }

    int buf = 0;
    for (int kt = 0; kt < 1024; kt += 32) {
        const bool has = (kt + 32 < 1024);
        if (has) {
            const int nxt = kt + 32;
            const u32t ao = (u32t)((buf ^ 1) * A_BUF * 2);
            const u32t bo = (u32t)((buf ^ 1) * B_BUF * 2);
            cp16(uAh + ao + aDst,      gAh + nxt);
            cp16(uAh + ao + aDst + 16, gAh + nxt + 8);
            cp16(uAl + ao + aDst,      gAl + nxt);
            cp16(uAl + ao + aDst + 16, gAl + nxt + 8);
            cp16(uBh + bo + bDst,      gBh + (size_t)nxt * 1024);
            cp16(uBh + bo + bDst + 16, gBh + (size_t)nxt * 1024 + 8);
            cp16(uBl + bo + bDst,      gBl + (size_t)nxt * 1024);
            cp16(uBl + bo + bDst + 16, gBl + (size_t)nxt * 1024 + 8);
            cp_commit();
            cp_wait1();
        } else {
            cp_wait0();
        }
        __syncthreads();

        const int ab = buf * A_BUF, bb = buf * B_BUF;
#pragma unroll
        for (int kk = 0; kk < 32; kk += 16) {
            FragA fah[2], fal[2];
#pragma unroll
            for (int mi = 0; mi < 2; mi++) {
                wmma::load_matrix_sync(fah[mi], &sAh[ab + (wm * 32 + mi * 16) * AK + kk], AK);
                wmma::load_matrix_sync(fal[mi], &sAl[ab + (wm * 32 + mi * 16) * AK + kk], AK);
            }
#pragma unroll
            for (int ni = 0; ni < 4; ni++) {
                FragB fbh, fbl;
                wmma::load_matrix_sync(fbh, &sBh[bb + kk * BN + wn * 64 + ni * 16], BN);
                wmma::load_matrix_sync(fbl, &sBl[bb + kk * BN + wn * 64 + ni * 16], BN);
#pragma unroll
                for (int mi = 0; mi < 2; mi++) {
                    wmma::mma_sync(acc[mi][ni], fah[mi], fbh, acc[mi][ni]);
                    wmma::mma_sync(acc[mi][ni], fah[mi], fbl, acc[mi][ni]);
                    wmma::mma_sync(acc[mi][ni], fal[mi], fbh, acc[mi][ni]);
                }
            }
        }
        __syncthreads();
        buf ^= 1;
    }

#pragma unroll
    for (int mi = 0; mi < 2; mi++)
#pragma unroll
        for (int ni = 0; ni < 4; ni++)
            wmma::store_matrix_sync(&stage[(wm * 32 + mi * 16) * 132 + wn * 64 + ni * 16],
                                    acc[mi][ni], 132, wmma::mem_row_major);
    __syncthreads();

    {
        const int r = tid >> 1;
        const int hf = (tid & 1) * 64;
        const float* src = stage + r * 132 + hf;
        if (Cf) {
            const float bv = bias ? bias[m0 + r] : 0.f;
            float* dst = Cf + (size_t)(m0 + r) * 1024 + n0 + hf;
#pragma unroll
            for (int j = 0; j < 16; j++) {
                float4 v = *(const float4*)(src + j * 4);
                v.x += bv; v.y += bv; v.z += bv; v.w += bv;
                *(float4*)(dst + j * 4) = v;
            }
        } else {
            size_t o = (size_t)(m0 + r) * 1024 + n0 + hf;
#pragma unroll
            for (int j = 0; j < 16; j++) {
                uint2 uh, ul;
                split4(*(const float4*)(src + j * 4), uh, ul);
                *(uint2*)(Ch + o + j * 4) = uh;
                *(uint2*)(Cl + o + j * 4) = ul;
            }
        }
    }
}

__global__ __launch_bounds__(256, 2) void k_proj_mma()
{
    int z = blockIdx.z;
    int p = z >> 2;   // 0=K,1=Q,2=V
    mma_gemm_body(g_w_hi + (size_t)p * E_ * E_, g_w_lo + (size_t)p * E_ * E_,
                  g_x_hi + (size_t)z * E_ * W_, g_x_lo + (size_t)z * E_ * W_,
                  nullptr, g_qkv_hi + (size_t)z * E_ * W_, g_qkv_lo + (size_t)z * E_ * W_,
                  nullptr);
}

__global__ __launch_bounds__(256, 2) void k_final_mma(
    const float* __restrict__ bias, float* __restrict__ out)
{
    int b = blockIdx.z;
    mma_gemm_body(g_w_hi + 3ull * E_ * E_, g_w_lo + 3ull * E_ * E_,
                  g_o_hi + (size_t)b * E_ * W_, g_o_lo + (size_t)b * E_ * W_,
                  out + (size_t)b * E_ * W_, nullptr, nullptr, bias);
}

// ---------------- fused attention (single pass, no max shift; V-load deferral) ----------------
#define FZ_LD 136
#define OFS_KH 0
#define OFS_KL 17408
#define OFS_QH 34816
#define OFS_QL 52224
#define OFS_PH 34816
#define OFS_PL 69632
#define OFS_S  104448
#define OFS_VH 172032
#define OFS_VL 189440
#define OFS_M  206848
#define OFS_L  207360
#define OFS_PART 207872
#define SMEM_FZ 209920

__global__ __launch_bounds__(256) void k_attn_fused()
{
    extern __shared__ __align__(128) char smem[];
    __nv_bfloat16* sKh = (__nv_bfloat16*)(smem + OFS_KH);
    __nv_bfloat16* sKl = (__nv_bfloat16*)(smem + OFS_KL);
    __nv_bfloat16* sQh = (__nv_bfloat16*)(smem + OFS_QH);
    __nv_bfloat16* sQl = (__nv_bfloat16*)(smem + OFS_QL);
    __nv_bfloat16* sPh = (__nv_bfloat16*)(smem + OFS_PH);   // overlays Q region
    __nv_bfloat16* sPl = (__nv_bfloat16*)(smem + OFS_PL);
    float* sS = (float*)(smem + OFS_S);                      // [128][132]
    __nv_bfloat16* sVh = (__nv_bfloat16*)(smem + OFS_VH);
    __nv_bfloat16* sVl = (__nv_bfloat16*)(smem + OFS_VL);
    float* sM = (float*)(smem + OFS_M);
    float* sL = (float*)(smem + OFS_L);
    float* sPart = (float*)(smem + OFS_PART);                // [4][128]

    const int kt = 7 - blockIdx.x;
    const int n0 = kt * 128;
    const int z = blockIdx.y;
    const int b = z >> 4, h = z & 15;
    const size_t qoff = (size_t)((4 + b) * E_ + h * D_) * W_;
    const size_t koff = (size_t)(b * E_ + h * D_) * W_;
    const size_t voff = (size_t)((8 + b) * E_ + h * D_) * W_;

    const int tid = threadIdx.x;
    const int w = tid >> 5;

    const int lrow = tid >> 2;
    const int lcb  = (tid & 3) * 32;

#pragma unroll
    for (int u = 0; u < 4; u++) {
        int col = lcb + u * 8;
        *(uint4*)(&sKh[lrow * FZ_LD + col]) = *(const uint4*)(g_qkv_hi + koff + (size_t)lrow * W_ + n0 + col);
        *(uint4*)(&sKl[lrow * FZ_LD + col]) = *(const uint4*)(g_qkv_lo + koff + (size_t)lrow * W_ + n0 + col);
    }
    if (tid < 128) sL[tid] = 0.f;

    const int cp = (tid & 63) * 2;
    const int rq = tid >> 6;

    const int swm = w & 3, swn = w >> 2;
    const int awm = w & 1, awn = w >> 1;

    FragC oacc[2][2];
#pragma unroll
    for (int mi = 0; mi < 2; mi++)
#pragma unroll
        for (int ni = 0; ni < 2; ni++) wmma::fill_fragment(oacc[mi][ni], 0.0f);

    for (int t = 0; t <= kt; t++) {
        __syncthreads();
        uint4 vh[4], vl[4];
#pragma unroll
        for (int u = 0; u < 4; u++) {
            int col = lcb + u * 8;
            vh[u] = *(const uint4*)(g_qkv_hi + voff + (size_t)lrow * W_ + t * 128 + col);
            vl[u] = *(const uint4*)(g_qkv_lo + voff + (size_t)lrow * W_ + t * 128 + col);
        }
#pragma unroll
        for (int u = 0; u < 4; u++) {
            int col = lcb + u * 8;
            *(uint4*)(&sQh[lrow * FZ_LD + col]) = *(const uint4*)(g_qkv_hi + qoff + (size_t)lrow * W_ + t * 128 + col);
            *(uint4*)(&sQl[lrow * FZ_LD + col]) = *(const uint4*)(g_qkv_lo + qoff + (size_t)lrow * W_ + t * 128 + col);
        }
        __syncthreads();

        FragC sacc[2][4];
#pragma unroll
        for (int mi = 0; mi < 2; mi++)
#pragma unroll
            for (int ni = 0; ni < 4; ni++) wmma::fill_fragment(sacc[mi][ni], 0.0f);
#pragma unroll
        for (int ks = 0; ks < 64; ks += 16) {
            FragAT fah[2], fal[2];
#pragma unroll
            for (int mi = 0; mi < 2; mi++) {
                wmma::load_matrix_sync(fah[mi], &sQh[ks * FZ_LD + swm * 32 + mi * 16], FZ_LD);
                wmma::load_matrix_sync(fal[mi], &sQl[ks * FZ_LD + swm * 32 + mi * 16], FZ_LD);
            }
#pragma unroll
            for (int ni = 0; ni < 4; ni++) {
                FragB fbh, fbl;
                wmma::load_matrix_sync(fbh, &sKh[ks * FZ_LD + swn * 64 + ni * 16], FZ_LD);
                wmma::load_matrix_sync(fbl, &sKl[ks * FZ_LD + swn * 64 + ni * 16], FZ_LD);
#pragma unroll
                for (int mi = 0; mi < 2; mi++) {
                    wmma::mma_sync(sacc[mi][ni], fah[mi], fbh, sacc[mi][ni]);
                    wmma::mma_sync(sacc[mi][ni], fah[mi], fbl, sacc[mi][ni]);
                    wmma::mma_sync(sacc[mi][ni], fal[mi], fbh, sacc[mi][ni]);
                }
            }
        }
#pragma unroll
        for (int mi = 0; mi < 2; mi++)
#pragma unroll
            for (int ni = 0; ni < 4; ni++)
                wmma::store_matrix_sync(&sS[(swm * 32 + mi * 16) * 132 + swn * 64 + ni * 16],
                                        sacc[mi][ni], 132, wmma::mem_row_major);
        __syncthreads();

        float l0 = 0.f, l1 = 0.f;
        const bool diag = (t == kt);
        for (int r = 0; r < 32; r++) {
            int ql = rq * 32 + r;
            float2 v = *(const float2*)(&sS[ql * 132 + cp]);
            float p0 = (!diag || ql <= cp)     ? __expf(v.x) : 0.f;
            float p1 = (!diag || ql <= cp + 1) ? __expf(v.y) : 0.f;
            l0 += p0; l1 += p1;
            __nv_bfloat16 h0 = __float2bfloat16_rn(p0);
            __nv_bfloat16 h1 = __float2bfloat16_rn(p1);
            __nv_bfloat16 g0 = __float2bfloat16_rn(p0 - __bfloat162float(h0));
            __nv_bfloat16 g1 = __float2bfloat16_rn(p1 - __bfloat162float(h1));
            *(u32t*)(&sPh[ql * FZ_LD + cp]) = (u32t)__bfloat16_as_ushort(h0) | ((u32t)__bfloat16_as_ushort(h1) << 16);
            *(u32t*)(&sPl[ql * FZ_LD + cp]) = (u32t)__bfloat16_as_ushort(g0) | ((u32t)__bfloat16_as_ushort(g1) << 16);
        }
#pragma unroll
        for (int u = 0; u < 4; u++) {
            int col = lcb + u * 8;
            *(uint4*)(&sVh[lrow * FZ_LD + col]) = vh[u];
            *(uint4*)(&sVl[lrow * FZ_LD + col]) = vl[u];
        }
        sPart[rq * 128 + cp]     = l0;
        sPart[rq * 128 + cp + 1] = l1;
        __syncthreads();
        if (tid < 128)
            sL[tid] += sPart[tid] + sPart[128 + tid] + sPart[256 + tid] + sPart[384 + tid];

#pragma unroll
        for (int ks = 0; ks < 128; ks += 16) {
            FragA fvh[2], fvl[2];
#pragma unroll
            for (int mi = 0; mi < 2; mi++) {
                wmma::load_matrix_sync(fvh[mi], &sVh[(awm * 32 + mi * 16) * FZ_LD + ks], FZ_LD);
                wmma::load_matrix_sync(fvl[mi], &sVl[(awm * 32 + mi * 16) * FZ_LD + ks], FZ_LD);
            }
#pragma unroll
            for (int ni = 0; ni < 2; ni++) {
                FragB fph, fpl;
                wmma::load_matrix_sync(fph, &sPh[ks * FZ_LD + awn * 32 + ni * 16], FZ_LD);
                wmma::load_matrix_sync(fpl, &sPl[ks * FZ_LD + awn * 32 + ni * 16], FZ_LD);
#pragma unroll
                for (int mi = 0; mi < 2; mi++) {
                    wmma::mma_sync(oacc[mi][ni], fvh[mi], fph, oacc[mi][ni]);
                    wmma::mma_sync(oacc[mi][ni], fvh[mi], fpl, oacc[mi][ni]);
                    wmma::mma_sync(oacc[mi][ni], fvl[mi], fph, oacc[mi][ni]);
                }
            }
        }
    }
    __syncthreads();

#pragma unroll
    for (int mi = 0; mi < 2; mi++)
#pragma unroll
        for (int ni = 0; ni < 2; ni++)
            wmma::store_matrix_sync(&sS[(awm * 32 + mi * 16) * 132 + awn * 32 + ni * 16],
                                    oacc[mi][ni], 132, wmma::mem_row_major);
    if (tid < 128) sM[tid] = 1.0f / (32.0f * sL[tid]);
    __syncthreads();

    {
        const size_t obase = (size_t)(b * E_ + h * D_ + lrow) * W_ + n0;
#pragma unroll
        for (int u = 0; u < 8; u++) {
            int col = lcb + u * 4;
            float4 v = *(const float4*)(&sS[lrow * 132 + col]);
            v.x *= sM[col]; v.y *= sM[col + 1]; v.z *= sM[col + 2]; v.w *= sM[col + 3];
            uint2 uh, ul;
            split4(v, uh, ul);
            *(uint2*)(g_o_hi + obase + col) = uh;
            *(uint2*)(g_o_lo + obase + col) = ul;
        }
    }
}

// ---------------------------------------------------------------------------
extern "C" void kernel_launch(void* const* d_in, const int* in_sizes, int n_in,
                              void* d_out, int out_size)
{
    const float* x  = (const float*)d_in[0];
    const float* LQ = (const float*)d_in[1];
    const float* LK = (const float*)d_in[2];
    const float* LV = (const float*)d_in[3];
    const float* Mw = (const float*)d_in[4];
    const float* bv = (const float*)d_in[5];
    float* out = (float*)d_out;

    cudaFuncSetAttribute(k_proj_mma,   cudaFuncAttributeMaxDynamicSharedMemorySize, SMEM_MMA);
    cudaFuncSetAttribute(k_final_mma,  cudaFuncAttributeMaxDynamicSharedMemorySize, SMEM_MMA);
    cudaFuncSetAttribute(k_attn_fused, cudaFuncAttributeMaxDynamicSharedMemorySize, SMEM_FZ);

    dim3 blk(256);

    k_split_w<<<1024, blk>>>(LK, 0);
    k_split_w<<<1024, blk>>>(LQ, 1);
    k_split_w<<<1024, blk>>>(LV, 2);
    k_split_w<<<1024, blk>>>(Mw, 3);
    k_split_x<<<12288, blk>>>(x);

    k_proj_mma  <<<dim3(8, 8, 12), blk, SMEM_MMA>>>();
    k_attn_fused<<<dim3(8, 64),    blk, SMEM_FZ>>>();
    k_final_mma <<<dim3(8, 8, 4),  blk, SMEM_MMA>>>(bv, out);
}